// round 10
// baseline (speedup 1.0000x reference)
#include <cuda_runtime.h>

#define N_NODES 8192
#define N_EDGES 8192
#define DEG 32
#define NNZ (N_EDGES * DEG)
#define D 32
#define CAP 128          // max node degree capacity (Poisson(32); fixed input << 128)
#define FULL 0xffffffffu

// Zero-fill slice split of the 16M-float4 output across the 4 fat kernels.
#define ZA_OFF 0
#define ZA_CNT (4 << 20)
#define ZB_OFF (4 << 20)
#define ZB_CNT (4 << 20)
#define ZC_OFF (8 << 20)
#define ZC_CNT (4 << 20)
#define ZD_OFF (12 << 20)
#define ZD_CNT (4 << 20)   // 4*4M = 16M = 8192*8192/4

// ---------------- scratch (device globals; no allocation) ----------------
__device__ __align__(16) int   g_dedup[NNZ];          // node idx or -1 (dup within edge)
__device__ int   g_cnt[N_NODES];                      // node degree ctr (zero-init at load;
                                                      //  reset each launch by k_nodefinal)
__device__ __align__(16) int   g_bkt[N_NODES * CAP];  // node -> edge ids (CSR buckets)
__device__ __align__(16) float g_t[N_EDGES * D];      // t_e = s_e @ W_l1
__device__ __align__(16) float g_x0b[N_NODES * D];    // x_0 after layer 1
__device__ __align__(16) float g_tb[N_EDGES];         // dot(t2_e, u_node) per edge
__device__ __align__(16) float g_b[N_EDGES];          // per-edge collapsed-MLP scalar
__device__ __align__(16) float g_u[2 * D];            // collapsed MLP weights
__device__ float g_c;                                 // collapsed MLP bias

// ---------------- k1: prep = zero slice + dedup + CSR build + collapse ------
__global__ void k_prep(float4* __restrict__ out, const int* __restrict__ node_idx,
                       const float* __restrict__ Wm1, const float* __restrict__ bm1,
                       const float* __restrict__ Wm2, const float* __restrict__ bm2,
                       const float* __restrict__ Wm3, const float* __restrict__ bm3) {
    int tid = blockIdx.x * blockDim.x + threadIdx.x;
    int nth = gridDim.x * blockDim.x;
    float4 z = make_float4(0.f, 0.f, 0.f, 0.f);
    for (int i = tid; i < ZA_CNT; i += nth) __stwt(&out[ZA_OFF + i], z);

    // dedup + CSR append: warp = one hyperedge (entries 32-aligned)
    int warp = tid >> 5, lane = tid & 31;
    int nwarp = nth >> 5;
    for (int e = warp; e < N_EDGES; e += nwarp) {
        int v = node_idx[e * DEG + lane];
        unsigned m = __match_any_sync(FULL, v);
        bool first = ((m & ((1u << lane) - 1u)) == 0u);
        g_dedup[e * DEG + lane] = first ? v : -1;
        if (first) {
            int pos = atomicAdd(&g_cnt[v], 1);
            if (pos < CAP) g_bkt[v * CAP + pos] = e;
        }
    }

    // collapse affine MLP in ONE warp (shfl-only):
    //   v3 = Wm3;  v2 = Wm2 @ v3;  u = Wm1 @ v2 (64);  c = bm1.v2 + bm2.v3 + bm3
    if (blockIdx.x == gridDim.x - 1 && threadIdx.x < 32) {
        int l = threadIdx.x;
        float w3 = Wm3[l];
        float v2 = 0.f;
        #pragma unroll
        for (int j = 0; j < D; j++) v2 += Wm2[l * D + j] * __shfl_sync(FULL, w3, j);
        float u0 = 0.f, u1 = 0.f;
        #pragma unroll
        for (int d = 0; d < D; d++) {
            float vd = __shfl_sync(FULL, v2, d);
            u0 += Wm1[l * D + d] * vd;          // node half (rows 0..31 of Wm1)
            u1 += Wm1[(l + 32) * D + d] * vd;   // edge half (rows 32..63)
        }
        g_u[l] = u0;
        g_u[l + 32] = u1;
        float p = bm1[l] * v2 + bm2[l] * w3;
        #pragma unroll
        for (int o = 16; o > 0; o >>= 1) p += __shfl_xor_sync(FULL, p, o);
        if (l == 0) g_c = p + bm3[0];
    }
}

// ---------------- k2: edge pass 1 — gather x0, linear, coalesced store ------
// s_e = sum_{unique n in e} x0[n];  t_e = s_e @ W_l1  -> g_t  (NO atomics)
__global__ void k_edge1(const float* __restrict__ x0, const float* __restrict__ W,
                        float4* __restrict__ out) {
    __shared__ float sW[D * D];
    for (int i = threadIdx.x; i < D * D; i += blockDim.x) sW[i] = W[i];
    __syncthreads();   // only protects sW; zero loop proceeds after

    int tid = blockIdx.x * blockDim.x + threadIdx.x;
    int nth = gridDim.x * blockDim.x;
    float4 z = make_float4(0.f, 0.f, 0.f, 0.f);
    for (int i = tid; i < ZB_CNT; i += nth) __stwt(&out[ZB_OFF + i], z);

    int warp = tid >> 5;
    int lane = tid & 31;
    if (warp >= N_EDGES) return;
    int myn = g_dedup[warp * DEG + lane];

    float s = 0.f;
    #pragma unroll
    for (int k = 0; k < DEG; k++) {
        int n = __shfl_sync(FULL, myn, k);
        if (n >= 0) s += x0[n * D + lane];
    }
    float t = 0.f;
    #pragma unroll
    for (int d = 0; d < D; d++)
        t += __shfl_sync(FULL, s, d) * sW[d * D + lane];
    g_t[warp * D + lane] = t;
}

// ---------------- k3: node pass 1 — CSR gather of t rows ------------------
// x0b[n] = sum_{e in bucket(n)} t_e   (coalesced 128B row gathers, no atomics)
__global__ void k_node1(float4* __restrict__ out) {
    int tid = blockIdx.x * blockDim.x + threadIdx.x;
    int nth = gridDim.x * blockDim.x;
    float4 z = make_float4(0.f, 0.f, 0.f, 0.f);
    for (int i = tid; i < ZC_CNT; i += nth) __stwt(&out[ZC_OFF + i], z);

    int warp = tid >> 5;
    int lane = tid & 31;
    if (warp >= N_NODES) return;
    int cnt = min(g_cnt[warp], CAP);
    const int* bkt = &g_bkt[warp * CAP];
    int e0 = (lane      < cnt) ? bkt[lane]      : -1;
    int e1 = (lane + 32 < cnt) ? bkt[lane + 32] : -1;
    int e2 = (lane + 64 < cnt) ? bkt[lane + 64] : -1;

    float s = 0.f;
    #pragma unroll
    for (int k = 0; k < 32; k++) {
        int e = __shfl_sync(FULL, e0, k);
        if (e >= 0) s += g_t[e * D + lane];
    }
    if (__any_sync(FULL, e1 >= 0)) {
        #pragma unroll
        for (int k = 0; k < 32; k++) {
            int e = __shfl_sync(FULL, e1, k);
            if (e >= 0) s += g_t[e * D + lane];
        }
    }
    if (__any_sync(FULL, e2 >= 0)) {
        #pragma unroll
        for (int k = 0; k < 32; k++) {
            int e = __shfl_sync(FULL, e2, k);
            if (e >= 0) s += g_t[e * D + lane];
        }
    }
    g_x0b[warp * D + lane] = s;
}

// ---------------- k4: edge pass 2 — gather x0b, produce per-edge scalars ----
// s = inc.T gather of x0b;  b[e] = dot(s, u_edge);
// t2 = s @ W_l2;  tb[e] = dot(t2, u_node)   (a[n] = sum tb over bucket later)
__global__ void k_edge2(const float* __restrict__ W, float4* __restrict__ out) {
    __shared__ float sW[D * D];
    for (int i = threadIdx.x; i < D * D; i += blockDim.x) sW[i] = W[i];
    __syncthreads();

    int tid = blockIdx.x * blockDim.x + threadIdx.x;
    int nth = gridDim.x * blockDim.x;
    float4 z = make_float4(0.f, 0.f, 0.f, 0.f);
    for (int i = tid; i < ZD_CNT; i += nth) __stwt(&out[ZD_OFF + i], z);

    int warp = tid >> 5;
    int lane = tid & 31;
    if (warp >= N_EDGES) return;
    int myn = g_dedup[warp * DEG + lane];

    float s = 0.f;
    #pragma unroll
    for (int k = 0; k < DEG; k++) {
        int n = __shfl_sync(FULL, myn, k);
        if (n >= 0) s += g_x0b[n * D + lane];
    }
    float t2 = 0.f;
    #pragma unroll
    for (int d = 0; d < D; d++)
        t2 += __shfl_sync(FULL, s, d) * sW[d * D + lane];

    float pb = s  * g_u[D + lane];   // edge half
    float pa = t2 * g_u[lane];       // node half
    #pragma unroll
    for (int o = 16; o > 0; o >>= 1) {
        pb += __shfl_xor_sync(FULL, pb, o);
        pa += __shfl_xor_sync(FULL, pa, o);
    }
    if (lane == 0) { g_b[warp] = pb; g_tb[warp] = pa; }
}

// ---------------- k5: node final — a[n] + row-local scatter + cnt reset ----
// a = sum tb over bucket(n);  out[n, e] = a + b[e] + c for each e in bucket.
__global__ void k_nodefinal(float* __restrict__ out) {
    int warp = (blockIdx.x * blockDim.x + threadIdx.x) >> 5;
    int lane = threadIdx.x & 31;
    if (warp >= N_NODES) return;
    int cnt = min(g_cnt[warp], CAP);
    const int* bkt = &g_bkt[warp * CAP];
    int e0 = (lane      < cnt) ? bkt[lane]      : -1;
    int e1 = (lane + 32 < cnt) ? bkt[lane + 32] : -1;
    int e2 = (lane + 64 < cnt) ? bkt[lane + 64] : -1;

    float a = 0.f;
    if (e0 >= 0) a += g_tb[e0];
    if (e1 >= 0) a += g_tb[e1];
    if (e2 >= 0) a += g_tb[e2];
    #pragma unroll
    for (int o = 16; o > 0; o >>= 1) a += __shfl_xor_sync(FULL, a, o);

    float v = a + g_c;
    float* row = out + (long)warp * N_EDGES;
    if (e0 >= 0) __stwt(&row[e0], v + g_b[e0]);
    if (e1 >= 0) __stwt(&row[e1], v + g_b[e1]);
    if (e2 >= 0) __stwt(&row[e2], v + g_b[e2]);

    if (lane == 0) g_cnt[warp] = 0;   // reset for next (graph-replayed) launch
}

// ---------------- launch ----------------
extern "C" void kernel_launch(void* const* d_in, const int* in_sizes, int n_in,
                              void* d_out, int out_size) {
    const float* x0   = (const float*)d_in[0];
    // d_in[1] = dense incidence (256MB) — intentionally unused
    const float* W_l1 = (const float*)d_in[2];
    const float* W_l2 = (const float*)d_in[3];
    const float* Wm1  = (const float*)d_in[4];
    const float* bm1  = (const float*)d_in[5];
    const float* Wm2  = (const float*)d_in[6];
    const float* bm2  = (const float*)d_in[7];
    const float* Wm3  = (const float*)d_in[8];
    const float* bm3  = (const float*)d_in[9];
    const int* node_idx = (const int*)d_in[10];
    float* out = (float*)d_out;

    k_prep     <<<2048, 256>>>((float4*)out, node_idx, Wm1, bm1, Wm2, bm2, Wm3, bm3);
    k_edge1    <<<2048, 256>>>(x0, W_l1, (float4*)out);
    k_node1    <<<2048, 256>>>((float4*)out);
    k_edge2    <<<2048, 256>>>(W_l2, (float4*)out);
    k_nodefinal<<<1024, 256>>>(out);
}